// round 1
// baseline (speedup 1.0000x reference)
#include <cuda_runtime.h>

#define BB 128
#define TT 256
#define DD 256
#define UU 256
#define ZZ 1024   // 4*U

// ---------------- scratch (device globals; no allocation allowed) ----------------
__device__ float g_xz[2][TT * BB * ZZ];       // [dir][t][b][u*4+g]   (reused across layers)
__device__ float g_h0[2][TT * BB * UU];       // layer-0 outputs [dir][t][b][u]
__device__ float g_h1[2][TT * BB * UU];       // layer-1 raw lstm outputs
__device__ float g_hT[2][2][UU * BB];         // [buf][dir][u][b]  double-buffered h^T
__device__ float g_c[2][UU * BB];             // [dir][u][b] cell state (CTA-exclusive)
__device__ float g_Wp[2][2][DD * ZZ];         // [layer][dir][k][u*4+g] permuted input weights
__device__ float g_Rp[2][2][UU * ZZ];         // [layer][dir][k][u*4+g] permuted recurrent weights
__device__ float g_bp[2][2][ZZ];              // permuted bias

// ---------------- MUFU-free fast math (keeps FFMA pipe busy, MUFU idle) ----------
__device__ __forceinline__ float fast_exp(float x) {
    x = fminf(fmaxf(x, -80.0f), 80.0f);
    float y = x * 1.442695041f;
    float t = y + 12582912.0f;            // round-to-nearest via magic
    float n = t - 12582912.0f;
    float f = y - n;                      // f in [-0.5, 0.5]
    int   ni = __float_as_int(t) - 0x4B400000;
    float p = 1.54035304e-4f;             // 2^f Taylor/minimax, deg 6 (err ~1e-7)
    p = fmaf(p, f, 1.33335581e-3f);
    p = fmaf(p, f, 9.61812910e-3f);
    p = fmaf(p, f, 5.55041087e-2f);
    p = fmaf(p, f, 2.40226507e-1f);
    p = fmaf(p, f, 6.93147182e-1f);
    p = fmaf(p, f, 1.0f);
    return p * __int_as_float((ni + 127) << 23);
}

__device__ __forceinline__ float fast_rcp(float a) {  // a > 0 here
    float r = __int_as_float(0x7EF311C3 - __float_as_int(a));
    r = r * fmaf(-a, r, 2.0f);
    r = r * fmaf(-a, r, 2.0f);
    r = r * fmaf(-a, r, 2.0f);
    return r;
}

__device__ __forceinline__ float sigm_(float x)  { return fast_rcp(1.0f + fast_exp(-x)); }
__device__ __forceinline__ float tanh_(float x)  { return fmaf(-2.0f, fast_rcp(1.0f + fast_exp(2.0f * x)), 1.0f); }

// ---------------- weight permutation: col (g*256+u) -> (u*4+g) --------------------
__global__ void prep_kernel(const float* __restrict__ kfw, const float* __restrict__ rfw,
                            const float* __restrict__ bfw, const float* __restrict__ kbw,
                            const float* __restrict__ rbw, const float* __restrict__ bbw) {
    int idx = blockIdx.x * blockDim.x + threadIdx.x;     // over 2*2*65536 = 1048576
    if (idx >= 2 * 2 * DD * ZZ) return;
    int e  = idx & (DD * ZZ - 1);      // 2^18 - 1
    int ld = idx >> 18;                // l*2 + d
    int l = ld >> 1, d = ld & 1;
    int k  = e >> 10;
    int uu = e & 1023;
    int u = uu >> 2, g = uu & 3;
    int src_col = g * UU + u;
    const float* Ksrc = d ? kbw : kfw;
    const float* Rsrc = d ? rbw : rfw;
    g_Wp[l][d][e] = Ksrc[l * DD * ZZ + k * ZZ + src_col];
    g_Rp[l][d][e] = Rsrc[l * UU * ZZ + k * ZZ + src_col];
    if (k == 0) {
        const float* bsrc = d ? bbw : bfw;
        g_bp[l][d][uu] = bsrc[l * ZZ + src_col];
    }
}

__global__ void zero_state_kernel() {
    int i = blockIdx.x * blockDim.x + threadIdx.x;   // 131072 threads
    float* hT = (float*)g_hT;
    float* c  = (float*)g_c;
    if (i < 2 * 2 * UU * BB) hT[i] = 0.0f;
    if (i < 2 * UU * BB)     c[i]  = 0.0f;
}

// ---------------- input projection: C[32768,1024] = A[32768,256] @ Wp + bp -------
__global__ __launch_bounds__(256) void proj_kernel(const float* __restrict__ x, int layer) {
    int dir = blockIdx.z;
    const float* A  = (layer == 0) ? x : g_h0[dir];
    const float* Wp = g_Wp[layer][dir];
    const float* bp = g_bp[layer][dir];
    float* C = g_xz[dir];
    const int m0 = blockIdx.y * 128;
    const int n0 = blockIdx.x * 128;
    __shared__ float As[8][128];
    __shared__ float Bs[8][128];
    int tid = threadIdx.x;
    int tm = (tid >> 4) << 3;
    int tn = (tid & 15) << 3;
    float acc[8][8];
#pragma unroll
    for (int i = 0; i < 8; i++)
#pragma unroll
        for (int j = 0; j < 8; j++) acc[i][j] = 0.0f;

    int arow = tid >> 1, akq = (tid & 1) << 2;
    int brow = tid >> 5, bc = (tid & 31) << 2;

    for (int k0 = 0; k0 < DD; k0 += 8) {
        float4 av = *(const float4*)(A + (m0 + arow) * DD + k0 + akq);
        As[akq + 0][arow] = av.x;
        As[akq + 1][arow] = av.y;
        As[akq + 2][arow] = av.z;
        As[akq + 3][arow] = av.w;
        *(float4*)&Bs[brow][bc] = *(const float4*)(Wp + (k0 + brow) * ZZ + n0 + bc);
        __syncthreads();
#pragma unroll
        for (int kk = 0; kk < 8; kk++) {
            float a[8], b[8];
            *(float4*)&a[0] = *(float4*)&As[kk][tm];
            *(float4*)&a[4] = *(float4*)&As[kk][tm + 4];
            *(float4*)&b[0] = *(float4*)&Bs[kk][tn];
            *(float4*)&b[4] = *(float4*)&Bs[kk][tn + 4];
#pragma unroll
            for (int i = 0; i < 8; i++)
#pragma unroll
                for (int j = 0; j < 8; j++)
                    acc[i][j] = fmaf(a[i], b[j], acc[i][j]);
        }
        __syncthreads();
    }
    float bv[8];
#pragma unroll
    for (int j = 0; j < 8; j++) bv[j] = bp[n0 + tn + j];
#pragma unroll
    for (int i = 0; i < 8; i++) {
        int m = m0 + tm + i;
        // layer0: A row m = b*256+t  ->  C row = t*128+b ; layer1: identity
        int crow = (layer == 0) ? ((m & 255) * BB + (m >> 8)) : m;
        float* cp = C + crow * ZZ + n0 + tn;
        float4 v0, v1;
        v0.x = acc[i][0] + bv[0]; v0.y = acc[i][1] + bv[1];
        v0.z = acc[i][2] + bv[2]; v0.w = acc[i][3] + bv[3];
        v1.x = acc[i][4] + bv[4]; v1.y = acc[i][5] + bv[5];
        v1.z = acc[i][6] + bv[6]; v1.w = acc[i][7] + bv[7];
        *(float4*)cp = v0;
        *(float4*)(cp + 4) = v1;
    }
}

// ---------------- one recurrence step, both directions -----------------------------
// grid (64,1,2), block 128. CTA owns units u0..u0+3 (16 z-cols), all 128 batch rows.
__global__ __launch_bounds__(128) void step_kernel(int layer, int s) {
    extern __shared__ float sm[];
    float* hs = sm;                  // 256*128 floats (h^T, k-major)
    float* Rs = sm + UU * BB;        // 256*16 floats
    int dir = blockIdx.z;
    int t = dir ? (TT - 1 - s) : s;
    int rd = s & 1, wr = rd ^ 1;
    int u0 = blockIdx.x << 2;
    int tid = threadIdx.x;

    // load h^T (prev step) into smem
    float4* hs4 = (float4*)hs;
    const float4* hT4 = (const float4*)g_hT[rd][dir];
#pragma unroll 4
    for (int i = tid; i < UU * BB / 4; i += 128) hs4[i] = hT4[i];
    // load R slice (permuted, contiguous 16 floats per k-row)
    const float* Rp = g_Rp[layer][dir] + (u0 << 2);
    for (int i = tid; i < UU * 16; i += 128) {
        int k = i >> 4, c = i & 15;
        Rs[i] = Rp[k * ZZ + c];
    }
    __syncthreads();

    int r  = tid & 31;     // batch group: rows 4r..4r+3
    int cg = tid >> 5;     // unit within tile: u = u0+cg, cols = 4 gates
    float acc[4][4];
#pragma unroll
    for (int i = 0; i < 4; i++)
#pragma unroll
        for (int j = 0; j < 4; j++) acc[i][j] = 0.0f;

    const float4* hsv = (const float4*)hs;   // [k*32 + r]
    const float4* Rsv = (const float4*)Rs;   // [k*4 + cg]
#pragma unroll 4
    for (int k = 0; k < UU; k++) {
        float4 hv = hsv[k * 32 + r];
        float4 rv = Rsv[k * 4 + cg];
        acc[0][0] = fmaf(hv.x, rv.x, acc[0][0]);
        acc[0][1] = fmaf(hv.x, rv.y, acc[0][1]);
        acc[0][2] = fmaf(hv.x, rv.z, acc[0][2]);
        acc[0][3] = fmaf(hv.x, rv.w, acc[0][3]);
        acc[1][0] = fmaf(hv.y, rv.x, acc[1][0]);
        acc[1][1] = fmaf(hv.y, rv.y, acc[1][1]);
        acc[1][2] = fmaf(hv.y, rv.z, acc[1][2]);
        acc[1][3] = fmaf(hv.y, rv.w, acc[1][3]);
        acc[2][0] = fmaf(hv.z, rv.x, acc[2][0]);
        acc[2][1] = fmaf(hv.z, rv.y, acc[2][1]);
        acc[2][2] = fmaf(hv.z, rv.z, acc[2][2]);
        acc[2][3] = fmaf(hv.z, rv.w, acc[2][3]);
        acc[3][0] = fmaf(hv.w, rv.x, acc[3][0]);
        acc[3][1] = fmaf(hv.w, rv.y, acc[3][1]);
        acc[3][2] = fmaf(hv.w, rv.z, acc[3][2]);
        acc[3][3] = fmaf(hv.w, rv.w, acc[3][3]);
    }

    int u = u0 + cg;
    int bbase = r << 2;
    const float* xz = g_xz[dir] + ((t * BB) << 10) + (u << 2);
    float4 cold = *(const float4*)(g_c[dir] + u * BB + bbase);
    float cv[4] = {cold.x, cold.y, cold.z, cold.w};
    float hnew[4];
#pragma unroll
    for (int i = 0; i < 4; i++) {
        float4 xv = *(const float4*)(xz + (bbase + i) * ZZ);
        float zi = acc[i][0] + xv.x;
        float zf = acc[i][1] + xv.y;
        float zg = acc[i][2] + xv.z;
        float zo = acc[i][3] + xv.w;
        float ig = sigm_(zi);
        float fg = sigm_(zf);
        float gg = tanh_(zg);
        float og = sigm_(zo);
        float cn = fmaf(fg, cv[i], ig * gg);
        cv[i] = cn;
        hnew[i] = og * tanh_(cn);
    }
    *(float4*)(g_c[dir] + u * BB + bbase)      = make_float4(cv[0], cv[1], cv[2], cv[3]);
    *(float4*)(g_hT[wr][dir] + u * BB + bbase) = make_float4(hnew[0], hnew[1], hnew[2], hnew[3]);

    // stage sequence output in smem for coalesced float4 store to [t][b][u]
    __syncthreads();                // all hs reads done -> safe to reuse smem
    float* stage = hs;              // 128*4 floats
#pragma unroll
    for (int i = 0; i < 4; i++) stage[((bbase + i) << 2) + cg] = hnew[i];
    __syncthreads();
    {
        float* outp = (layer == 0 ? g_h0[dir] : g_h1[dir]) + ((t * BB) << 8);
        float4 v = ((float4*)stage)[tid];
        *(float4*)(outp + tid * UU + u0) = v;
    }
}

// ---------------- merge: out[b][t][u] = 0.5*(h1f + h0f + h1b + h0b) ---------------
__global__ void merge_kernel(float* __restrict__ out) {
    int i = blockIdx.x * blockDim.x + threadIdx.x;   // over 2097152 float4
    if (i >= TT * BB * UU / 4) return;
    int u4 = i & 63;
    int b  = (i >> 6) & 127;
    int t  = i >> 13;
    const float4 a = ((const float4*)g_h1[0])[i];
    const float4 c = ((const float4*)g_h0[0])[i];
    const float4 d = ((const float4*)g_h1[1])[i];
    const float4 e = ((const float4*)g_h0[1])[i];
    float4 rshort;
    rshort.x = 0.5f * (a.x + c.x + d.x + e.x);
    rshort.y = 0.5f * (a.y + c.y + d.y + e.y);
    rshort.z = 0.5f * (a.z + c.z + d.z + e.z);
    rshort.w = 0.5f * (a.w + c.w + d.w + e.w);
    ((float4*)out)[((b * TT + t) << 6) + u4] = rshort;
}

// ---------------- launch ----------------------------------------------------------
extern "C" void kernel_launch(void* const* d_in, const int* in_sizes, int n_in,
                              void* d_out, int out_size) {
    const float* x   = (const float*)d_in[0];
    const float* kfw = (const float*)d_in[1];
    const float* rfw = (const float*)d_in[2];
    const float* bfw = (const float*)d_in[3];
    const float* kbw = (const float*)d_in[4];
    const float* rbw = (const float*)d_in[5];
    const float* bbw = (const float*)d_in[6];
    float* out = (float*)d_out;

    const int step_smem = (UU * BB + UU * 16) * (int)sizeof(float);  // 147456
    cudaFuncSetAttribute(step_kernel, cudaFuncAttributeMaxDynamicSharedMemorySize, step_smem);

    prep_kernel<<<4096, 256>>>(kfw, rfw, bfw, kbw, rbw, bbw);
    for (int layer = 0; layer < 2; layer++) {
        zero_state_kernel<<<512, 256>>>();
        proj_kernel<<<dim3(8, 256, 2), 256>>>(x, layer);
        for (int s = 0; s < TT; s++)
            step_kernel<<<dim3(64, 1, 2), 128, step_smem>>>(layer, s);
    }
    merge_kernel<<<8192, 256>>>(out);
}

// round 2
// speedup vs baseline: 1.0013x; 1.0013x over previous
#include <cuda_runtime.h>

#define BB 128
#define TT 256
#define DD 256
#define UU 256
#define ZZ 1024   // 4*U

// ---------------- scratch (device globals; no allocation allowed) ----------------
__device__ float g_xz[2][TT * BB * ZZ];       // [dir][t][b][u*4+g]   (reused across layers)
__device__ float g_h0[2][TT * BB * UU];       // layer-0 outputs [dir][t][b][u]
__device__ float g_h1[2][TT * BB * UU];       // layer-1 raw lstm outputs
__device__ float g_hT[2][2][UU * BB];         // [buf][dir][u][b]  double-buffered h^T
__device__ float g_c[2][UU * BB];             // [dir][u][b] cell state (CTA-exclusive)
__device__ float g_Wp[2][2][DD * ZZ];         // [layer][dir][k][u*4+g] permuted input weights
__device__ float g_Rp[2][2][UU * ZZ];         // [layer][dir][k][u*4+g] permuted recurrent weights
__device__ float g_bp[2][2][ZZ];              // permuted bias

// ---------------- MUFU-free fast math (keeps FFMA pipe busy, MUFU idle) ----------
__device__ __forceinline__ float fast_exp(float x) {
    x = fminf(fmaxf(x, -80.0f), 80.0f);
    float y = x * 1.442695041f;
    float t = y + 12582912.0f;            // round-to-nearest via magic
    float n = t - 12582912.0f;
    float f = y - n;                      // f in [-0.5, 0.5]
    int   ni = __float_as_int(t) - 0x4B400000;
    float p = 1.54035304e-4f;             // 2^f Taylor/minimax, deg 6 (err ~1e-7)
    p = fmaf(p, f, 1.33335581e-3f);
    p = fmaf(p, f, 9.61812910e-3f);
    p = fmaf(p, f, 5.55041087e-2f);
    p = fmaf(p, f, 2.40226507e-1f);
    p = fmaf(p, f, 6.93147182e-1f);
    p = fmaf(p, f, 1.0f);
    return p * __int_as_float((ni + 127) << 23);
}

__device__ __forceinline__ float fast_rcp(float a) {  // a > 0 here
    float r = __int_as_float(0x7EF311C3 - __float_as_int(a));
    r = r * fmaf(-a, r, 2.0f);
    r = r * fmaf(-a, r, 2.0f);
    r = r * fmaf(-a, r, 2.0f);
    return r;
}

__device__ __forceinline__ float sigm_(float x)  { return fast_rcp(1.0f + fast_exp(-x)); }
__device__ __forceinline__ float tanh_(float x)  { return fmaf(-2.0f, fast_rcp(1.0f + fast_exp(2.0f * x)), 1.0f); }

// ---------------- weight permutation: col (g*256+u) -> (u*4+g) --------------------
__global__ void prep_kernel(const float* __restrict__ kfw, const float* __restrict__ rfw,
                            const float* __restrict__ bfw, const float* __restrict__ kbw,
                            const float* __restrict__ rbw, const float* __restrict__ bbw) {
    int idx = blockIdx.x * blockDim.x + threadIdx.x;     // over 2*2*65536 = 1048576
    if (idx >= 2 * 2 * DD * ZZ) return;
    int e  = idx & (DD * ZZ - 1);      // 2^18 - 1
    int ld = idx >> 18;                // l*2 + d
    int l = ld >> 1, d = ld & 1;
    int k  = e >> 10;
    int uu = e & 1023;
    int u = uu >> 2, g = uu & 3;
    int src_col = g * UU + u;
    const float* Ksrc = d ? kbw : kfw;
    const float* Rsrc = d ? rbw : rfw;
    g_Wp[l][d][e] = Ksrc[l * DD * ZZ + k * ZZ + src_col];
    g_Rp[l][d][e] = Rsrc[l * UU * ZZ + k * ZZ + src_col];
    if (k == 0) {
        const float* bsrc = d ? bbw : bfw;
        g_bp[l][d][uu] = bsrc[l * ZZ + src_col];
    }
}

__global__ void zero_state_kernel() {
    int i = blockIdx.x * blockDim.x + threadIdx.x;   // 131072 threads
    float* hT = (float*)g_hT;
    float* c  = (float*)g_c;
    if (i < 2 * 2 * UU * BB) hT[i] = 0.0f;
    if (i < 2 * UU * BB)     c[i]  = 0.0f;
}

// ---------------- input projection: C[32768,1024] = A[32768,256] @ Wp + bp -------
__global__ __launch_bounds__(256) void proj_kernel(const float* __restrict__ x, int layer) {
    int dir = blockIdx.z;
    const float* A  = (layer == 0) ? x : g_h0[dir];
    const float* Wp = g_Wp[layer][dir];
    const float* bp = g_bp[layer][dir];
    float* C = g_xz[dir];
    const int m0 = blockIdx.y * 128;
    const int n0 = blockIdx.x * 128;
    __shared__ float As[8][128];
    __shared__ float Bs[8][128];
    int tid = threadIdx.x;
    int tm = (tid >> 4) << 3;
    int tn = (tid & 15) << 3;
    float acc[8][8];
#pragma unroll
    for (int i = 0; i < 8; i++)
#pragma unroll
        for (int j = 0; j < 8; j++) acc[i][j] = 0.0f;

    int arow = tid >> 1, akq = (tid & 1) << 2;
    int brow = tid >> 5, bc = (tid & 31) << 2;

    for (int k0 = 0; k0 < DD; k0 += 8) {
        float4 av = *(const float4*)(A + (m0 + arow) * DD + k0 + akq);
        As[akq + 0][arow] = av.x;
        As[akq + 1][arow] = av.y;
        As[akq + 2][arow] = av.z;
        As[akq + 3][arow] = av.w;
        *(float4*)&Bs[brow][bc] = *(const float4*)(Wp + (k0 + brow) * ZZ + n0 + bc);
        __syncthreads();
#pragma unroll
        for (int kk = 0; kk < 8; kk++) {
            float a[8], b[8];
            *(float4*)&a[0] = *(float4*)&As[kk][tm];
            *(float4*)&a[4] = *(float4*)&As[kk][tm + 4];
            *(float4*)&b[0] = *(float4*)&Bs[kk][tn];
            *(float4*)&b[4] = *(float4*)&Bs[kk][tn + 4];
#pragma unroll
            for (int i = 0; i < 8; i++)
#pragma unroll
                for (int j = 0; j < 8; j++)
                    acc[i][j] = fmaf(a[i], b[j], acc[i][j]);
        }
        __syncthreads();
    }
    float bv[8];
#pragma unroll
    for (int j = 0; j < 8; j++) bv[j] = bp[n0 + tn + j];
#pragma unroll
    for (int i = 0; i < 8; i++) {
        int m = m0 + tm + i;
        // layer0: A row m = b*256+t  ->  C row = t*128+b ; layer1: identity
        int crow = (layer == 0) ? ((m & 255) * BB + (m >> 8)) : m;
        float* cp = C + crow * ZZ + n0 + tn;
        float4 v0, v1;
        v0.x = acc[i][0] + bv[0]; v0.y = acc[i][1] + bv[1];
        v0.z = acc[i][2] + bv[2]; v0.w = acc[i][3] + bv[3];
        v1.x = acc[i][4] + bv[4]; v1.y = acc[i][5] + bv[5];
        v1.z = acc[i][6] + bv[6]; v1.w = acc[i][7] + bv[7];
        *(float4*)cp = v0;
        *(float4*)(cp + 4) = v1;
    }
}

// ---------------- one recurrence step, both directions -----------------------------
// grid (64,1,2), block 128. CTA owns units u0..u0+3 (16 z-cols), all 128 batch rows.
__global__ __launch_bounds__(128) void step_kernel(int layer, int s) {
    extern __shared__ float sm[];
    float* hs = sm;                  // 256*128 floats (h^T, k-major)
    float* Rs = sm + UU * BB;        // 256*16 floats
    int dir = blockIdx.z;
    int t = dir ? (TT - 1 - s) : s;
    int rd = s & 1, wr = rd ^ 1;
    int u0 = blockIdx.x << 2;
    int tid = threadIdx.x;

    // load h^T (prev step) into smem
    float4* hs4 = (float4*)hs;
    const float4* hT4 = (const float4*)g_hT[rd][dir];
#pragma unroll 4
    for (int i = tid; i < UU * BB / 4; i += 128) hs4[i] = hT4[i];
    // load R slice (permuted, contiguous 16 floats per k-row)
    const float* Rp = g_Rp[layer][dir] + (u0 << 2);
    for (int i = tid; i < UU * 16; i += 128) {
        int k = i >> 4, c = i & 15;
        Rs[i] = Rp[k * ZZ + c];
    }
    __syncthreads();

    int r  = tid & 31;     // batch group: rows 4r..4r+3
    int cg = tid >> 5;     // unit within tile: u = u0+cg, cols = 4 gates
    float acc[4][4];
#pragma unroll
    for (int i = 0; i < 4; i++)
#pragma unroll
        for (int j = 0; j < 4; j++) acc[i][j] = 0.0f;

    const float4* hsv = (const float4*)hs;   // [k*32 + r]
    const float4* Rsv = (const float4*)Rs;   // [k*4 + cg]
#pragma unroll 4
    for (int k = 0; k < UU; k++) {
        float4 hv = hsv[k * 32 + r];
        float4 rv = Rsv[k * 4 + cg];
        acc[0][0] = fmaf(hv.x, rv.x, acc[0][0]);
        acc[0][1] = fmaf(hv.x, rv.y, acc[0][1]);
        acc[0][2] = fmaf(hv.x, rv.z, acc[0][2]);
        acc[0][3] = fmaf(hv.x, rv.w, acc[0][3]);
        acc[1][0] = fmaf(hv.y, rv.x, acc[1][0]);
        acc[1][1] = fmaf(hv.y, rv.y, acc[1][1]);
        acc[1][2] = fmaf(hv.y, rv.z, acc[1][2]);
        acc[1][3] = fmaf(hv.y, rv.w, acc[1][3]);
        acc[2][0] = fmaf(hv.z, rv.x, acc[2][0]);
        acc[2][1] = fmaf(hv.z, rv.y, acc[2][1]);
        acc[2][2] = fmaf(hv.z, rv.z, acc[2][2]);
        acc[2][3] = fmaf(hv.z, rv.w, acc[2][3]);
        acc[3][0] = fmaf(hv.w, rv.x, acc[3][0]);
        acc[3][1] = fmaf(hv.w, rv.y, acc[3][1]);
        acc[3][2] = fmaf(hv.w, rv.z, acc[3][2]);
        acc[3][3] = fmaf(hv.w, rv.w, acc[3][3]);
    }

    int u = u0 + cg;
    int bbase = r << 2;
    const float* xz = g_xz[dir] + ((t * BB) << 10) + (u << 2);
    float4 cold = *(const float4*)(g_c[dir] + u * BB + bbase);
    float cv[4] = {cold.x, cold.y, cold.z, cold.w};
    float hnew[4];
#pragma unroll
    for (int i = 0; i < 4; i++) {
        float4 xv = *(const float4*)(xz + (bbase + i) * ZZ);
        float zi = acc[i][0] + xv.x;
        float zf = acc[i][1] + xv.y;
        float zg = acc[i][2] + xv.z;
        float zo = acc[i][3] + xv.w;
        float ig = sigm_(zi);
        float fg = sigm_(zf);
        float gg = tanh_(zg);
        float og = sigm_(zo);
        float cn = fmaf(fg, cv[i], ig * gg);
        cv[i] = cn;
        hnew[i] = og * tanh_(cn);
    }
    *(float4*)(g_c[dir] + u * BB + bbase)      = make_float4(cv[0], cv[1], cv[2], cv[3]);
    *(float4*)(g_hT[wr][dir] + u * BB + bbase) = make_float4(hnew[0], hnew[1], hnew[2], hnew[3]);

    // stage sequence output in smem for coalesced float4 store to [t][b][u]
    __syncthreads();                // all hs reads done -> safe to reuse smem
    float* stage = hs;              // 128*4 floats
#pragma unroll
    for (int i = 0; i < 4; i++) stage[((bbase + i) << 2) + cg] = hnew[i];
    __syncthreads();
    {
        float* outp = (layer == 0 ? g_h0[dir] : g_h1[dir]) + ((t * BB) << 8);
        float4 v = ((float4*)stage)[tid];
        *(float4*)(outp + tid * UU + u0) = v;
    }
}

// ---------------- merge: out[b][t][u] = 0.5*(h1f + h0f + h1b + h0b) ---------------
__global__ void merge_kernel(float* __restrict__ out) {
    int i = blockIdx.x * blockDim.x + threadIdx.x;   // over 2097152 float4
    if (i >= TT * BB * UU / 4) return;
    int u4 = i & 63;
    int b  = (i >> 6) & 127;
    int t  = i >> 13;
    const float4 a = ((const float4*)g_h1[0])[i];
    const float4 c = ((const float4*)g_h0[0])[i];
    const float4 d = ((const float4*)g_h1[1])[i];
    const float4 e = ((const float4*)g_h0[1])[i];
    float4 rshort;
    rshort.x = 0.5f * (a.x + c.x + d.x + e.x);
    rshort.y = 0.5f * (a.y + c.y + d.y + e.y);
    rshort.z = 0.5f * (a.z + c.z + d.z + e.z);
    rshort.w = 0.5f * (a.w + c.w + d.w + e.w);
    ((float4*)out)[((b * TT + t) << 6) + u4] = rshort;
}

// ---------------- launch ----------------------------------------------------------
extern "C" void kernel_launch(void* const* d_in, const int* in_sizes, int n_in,
                              void* d_out, int out_size) {
    const float* x   = (const float*)d_in[0];
    const float* kfw = (const float*)d_in[1];
    const float* rfw = (const float*)d_in[2];
    const float* bfw = (const float*)d_in[3];
    const float* kbw = (const float*)d_in[4];
    const float* rbw = (const float*)d_in[5];
    const float* bbw = (const float*)d_in[6];
    float* out = (float*)d_out;

    const int step_smem = (UU * BB + UU * 16) * (int)sizeof(float);  // 147456
    cudaFuncSetAttribute(step_kernel, cudaFuncAttributeMaxDynamicSharedMemorySize, step_smem);

    prep_kernel<<<4096, 256>>>(kfw, rfw, bfw, kbw, rbw, bbw);
    for (int layer = 0; layer < 2; layer++) {
        zero_state_kernel<<<512, 256>>>();
        proj_kernel<<<dim3(8, 256, 2), 256>>>(x, layer);
        for (int s = 0; s < TT; s++)
            step_kernel<<<dim3(64, 1, 2), 128, step_smem>>>(layer, s);
    }
    merge_kernel<<<8192, 256>>>(out);
}

// round 3
// speedup vs baseline: 1.8704x; 1.8680x over previous
#include <cuda_runtime.h>

#define BB 128
#define TT 256
#define DD 256
#define UU 256
#define ZZ 1024   // 4*U
#define NCTA 128

// ---------------- scratch (device globals; no allocation allowed) ----------------
__device__ float g_xz[2][TT * BB * ZZ];       // [dir][t][b][u*4+g]
__device__ float g_h0[2][TT * BB * UU];       // layer-0 outputs [dir][t][b][u]
__device__ float g_h1[2][TT * BB * UU];       // layer-1 raw lstm outputs
__device__ float g_hT[2][2][UU * BB];         // [buf][dir][u][b] double-buffered h^T
__device__ float g_Wp[2][2][DD * ZZ];         // [layer][dir][k][u*4+g]
__device__ float g_Rp[2][2][UU * ZZ];         // [layer][dir][k][u*4+g]
__device__ float g_bp[2][2][ZZ];
__device__ int          g_count;              // grid barrier
__device__ volatile int g_gen;

// ---------------- packed f32x2 (FFMA2) helpers ------------------------------------
__device__ __forceinline__ void fma2(unsigned long long& d, unsigned long long a,
                                     unsigned long long b) {
    asm("fma.rn.f32x2 %0, %1, %2, %0;" : "+l"(d) : "l"(a), "l"(b));
}
__device__ __forceinline__ void add2(unsigned long long& d, unsigned long long a) {
    asm("add.rn.f32x2 %0, %0, %1;" : "+l"(d) : "l"(a));
}
__device__ __forceinline__ unsigned long long pack2(float x) {
    unsigned long long d; unsigned int u = __float_as_uint(x);
    asm("mov.b64 %0, {%1, %1};" : "=l"(d) : "r"(u));
    return d;
}
__device__ __forceinline__ void unpack2(unsigned long long v, float& lo, float& hi) {
    unsigned int a, b;
    asm("mov.b64 {%0, %1}, %2;" : "=r"(a), "=r"(b) : "l"(v));
    lo = __uint_as_float(a); hi = __uint_as_float(b);
}

// ---------------- MUFU-free fast math ---------------------------------------------
__device__ __forceinline__ float fast_exp(float x) {
    x = fminf(fmaxf(x, -80.0f), 80.0f);
    float y = x * 1.442695041f;
    float t = y + 12582912.0f;
    float n = t - 12582912.0f;
    float f = y - n;
    int   ni = __float_as_int(t) - 0x4B400000;
    float p = 1.54035304e-4f;
    p = fmaf(p, f, 1.33335581e-3f);
    p = fmaf(p, f, 9.61812910e-3f);
    p = fmaf(p, f, 5.55041087e-2f);
    p = fmaf(p, f, 2.40226507e-1f);
    p = fmaf(p, f, 6.93147182e-1f);
    p = fmaf(p, f, 1.0f);
    return p * __int_as_float((ni + 127) << 23);
}
__device__ __forceinline__ float fast_rcp(float a) {
    float r = __int_as_float(0x7EF311C3 - __float_as_int(a));
    r = r * fmaf(-a, r, 2.0f);
    r = r * fmaf(-a, r, 2.0f);
    r = r * fmaf(-a, r, 2.0f);
    return r;
}
__device__ __forceinline__ float sigm_(float x) { return fast_rcp(1.0f + fast_exp(-x)); }
__device__ __forceinline__ float tanh_(float x) { return fmaf(-2.0f, fast_rcp(1.0f + fast_exp(2.0f * x)), 1.0f); }

// ---------------- weight permutation: col (g*256+u) -> (u*4+g) --------------------
__global__ void prep_kernel(const float* __restrict__ kfw, const float* __restrict__ rfw,
                            const float* __restrict__ bfw, const float* __restrict__ kbw,
                            const float* __restrict__ rbw, const float* __restrict__ bbw) {
    int idx = blockIdx.x * blockDim.x + threadIdx.x;
    if (idx >= 2 * 2 * DD * ZZ) return;
    int e  = idx & (DD * ZZ - 1);
    int ld = idx >> 18;
    int l = ld >> 1, d = ld & 1;
    int k  = e >> 10;
    int uu = e & 1023;
    int u = uu >> 2, g = uu & 3;
    int src_col = g * UU + u;
    const float* Ksrc = d ? kbw : kfw;
    const float* Rsrc = d ? rbw : rfw;
    g_Wp[l][d][e] = Ksrc[l * DD * ZZ + k * ZZ + src_col];
    g_Rp[l][d][e] = Rsrc[l * UU * ZZ + k * ZZ + src_col];
    if (k == 0) {
        const float* bsrc = d ? bbw : bfw;
        g_bp[l][d][uu] = bsrc[l * ZZ + src_col];
    }
}

// ---------------- input projection (FFMA2 double-pumped) ---------------------------
__global__ __launch_bounds__(256) void proj_kernel(const float* __restrict__ x, int layer) {
    int dir = blockIdx.z;
    const float* A  = (layer == 0) ? x : g_h0[dir];
    const float* Wp = g_Wp[layer][dir];
    const float* bp = g_bp[layer][dir];
    float* C = g_xz[dir];
    const int m0 = blockIdx.y * 128;
    const int n0 = blockIdx.x * 128;
    __shared__ float As[8][128];
    __shared__ float Bs[8][128];
    int tid = threadIdx.x;
    int tm = (tid >> 4) << 3;
    int tn = (tid & 15) << 3;
    unsigned long long acc2[8][4];
#pragma unroll
    for (int i = 0; i < 8; i++)
#pragma unroll
        for (int j = 0; j < 4; j++) acc2[i][j] = 0ULL;

    int arow = tid >> 1, akq = (tid & 1) << 2;
    int brow = tid >> 5, bc = (tid & 31) << 2;

    for (int k0 = 0; k0 < DD; k0 += 8) {
        float4 av = *(const float4*)(A + (m0 + arow) * DD + k0 + akq);
        As[akq + 0][arow] = av.x;
        As[akq + 1][arow] = av.y;
        As[akq + 2][arow] = av.z;
        As[akq + 3][arow] = av.w;
        *(float4*)&Bs[brow][bc] = *(const float4*)(Wp + (k0 + brow) * ZZ + n0 + bc);
        __syncthreads();
#pragma unroll
        for (int kk = 0; kk < 8; kk++) {
            float a[8];
            *(float4*)&a[0] = *(float4*)&As[kk][tm];
            *(float4*)&a[4] = *(float4*)&As[kk][tm + 4];
            ulonglong2 b01 = *(const ulonglong2*)&Bs[kk][tn];
            ulonglong2 b23 = *(const ulonglong2*)&Bs[kk][tn + 4];
#pragma unroll
            for (int i = 0; i < 8; i++) {
                unsigned long long ai = pack2(a[i]);
                fma2(acc2[i][0], ai, b01.x);
                fma2(acc2[i][1], ai, b01.y);
                fma2(acc2[i][2], ai, b23.x);
                fma2(acc2[i][3], ai, b23.y);
            }
        }
        __syncthreads();
    }
    float bv[8];
#pragma unroll
    for (int j = 0; j < 8; j++) bv[j] = bp[n0 + tn + j];
#pragma unroll
    for (int i = 0; i < 8; i++) {
        int m = m0 + tm + i;
        int crow = (layer == 0) ? ((m & 255) * BB + (m >> 8)) : m;
        float* cp = C + (size_t)crow * ZZ + n0 + tn;
        float c0, c1, c2, c3, c4, c5, c6, c7;
        unpack2(acc2[i][0], c0, c1);
        unpack2(acc2[i][1], c2, c3);
        unpack2(acc2[i][2], c4, c5);
        unpack2(acc2[i][3], c6, c7);
        float4 v0, v1;
        v0.x = c0 + bv[0]; v0.y = c1 + bv[1]; v0.z = c2 + bv[2]; v0.w = c3 + bv[3];
        v1.x = c4 + bv[4]; v1.y = c5 + bv[5]; v1.z = c6 + bv[6]; v1.w = c7 + bv[7];
        *(float4*)cp = v0;
        *(float4*)(cp + 4) = v1;
    }
}

// ---------------- persistent recurrence scan (one launch per layer) ----------------
// grid 128 CTAs x 256 threads. CTA = (dir, batch-quarter 32b, z-slice 64zc = 16 units).
// k-split x2 across thread halves. R resident in smem, c in registers.
__global__ __launch_bounds__(256, 1) void scan_kernel(int layer) {
    extern __shared__ float sm[];
    float* Rs = sm;                                   // 256*64  = 64 KB
    float* hs = sm + UU * 64;                         // 256*32  = 32 KB
    unsigned long long* red = (unsigned long long*)(hs + UU * 32);  // 128*8 u64 = 8 KB
    float* stage = (float*)(red + 128 * 8);           // 32*16 = 2 KB

    int bid = blockIdx.x;
    int dir  = bid >> 6;
    int rest = bid & 63;
    int b0  = (rest >> 4) * 32;      // batch quarter
    int zi  = rest & 15;             // z slice
    int zc0 = zi * 64;
    int u0  = zi * 16;
    int tid = threadIdx.x;
    int kh   = tid >> 7;             // k half
    int wtid = tid & 127;
    int zg  = wtid & 15;             // unit within slice
    int bgr = wtid >> 4;             // batch group of 4

    // load R slice once (resident for all 256 steps)
    {
        const float* Rp = g_Rp[layer][dir];
        float4* Rs4 = (float4*)Rs;
        for (int idx = tid; idx < 4096; idx += 256) {
            int k = idx >> 4, c = idx & 15;
            Rs4[idx] = *(const float4*)(Rp + k * ZZ + zc0 + c * 4);
        }
    }
    float cc[4] = {0.0f, 0.0f, 0.0f, 0.0f};
    const float* xzb  = g_xz[dir];
    float*       outb = (layer == 0) ? g_h0[dir] : g_h1[dir];
    __syncthreads();

    for (int s = 0; s < TT; s++) {
        int t  = dir ? (TT - 1 - s) : s;
        int rd = s & 1, wr = rd ^ 1;

        // load h^T slice [256 k][32 b] (L2-coherent loads; L1 is stale across barriers)
        float4* hs4 = (float4*)hs;
        if (s == 0) {
            for (int idx = tid; idx < 2048; idx += 256)
                hs4[idx] = make_float4(0.f, 0.f, 0.f, 0.f);
        } else {
            const float4* src = (const float4*)(g_hT[rd][dir]);
            for (int idx = tid; idx < 2048; idx += 256) {
                int k = idx >> 3, q = idx & 7;
                hs4[idx] = __ldcg(src + k * 32 + (b0 >> 2) + q);
            }
        }
        __syncthreads();

        // prefetch xz for gate phase (kh0 only) — hides under GEMM
        float4 xv[4];
        if (kh == 0) {
            const float* xp = xzb + (size_t)(t * BB + b0 + bgr * 4) * ZZ + zc0 + zg * 4;
#pragma unroll
            for (int i = 0; i < 4; i++) xv[i] = *(const float4*)(xp + i * ZZ);
        }

        // GEMM half: acc(4b x 4zc) over 128 k, packed f32x2 over gate pairs
        unsigned long long acc[8];
#pragma unroll
        for (int j = 0; j < 8; j++) acc[j] = 0ULL;
        {
            const float* hrow = hs + kh * 128 * 32 + bgr * 4;
            const float* rrow = Rs + kh * 128 * 64 + zg * 4;
#pragma unroll 4
            for (int k = 0; k < 128; k++) {
                float4 hv = *(const float4*)(hrow + k * 32);
                ulonglong2 rv = *(const ulonglong2*)(rrow + k * 64);
                unsigned long long h0 = pack2(hv.x), h1 = pack2(hv.y);
                unsigned long long h2 = pack2(hv.z), h3 = pack2(hv.w);
                fma2(acc[0], h0, rv.x); fma2(acc[1], h0, rv.y);
                fma2(acc[2], h1, rv.x); fma2(acc[3], h1, rv.y);
                fma2(acc[4], h2, rv.x); fma2(acc[5], h2, rv.y);
                fma2(acc[6], h3, rv.x); fma2(acc[7], h3, rv.y);
            }
        }
        // cross-half reduction
        if (kh == 1) {
#pragma unroll
            for (int j = 0; j < 8; j++) red[wtid * 8 + j] = acc[j];
        }
        __syncthreads();
        if (kh == 0) {
#pragma unroll
            for (int j = 0; j < 8; j++) add2(acc[j], red[wtid * 8 + j]);
            float hnew[4];
#pragma unroll
            for (int i = 0; i < 4; i++) {
                float z0, z1, z2, z3;
                unpack2(acc[i * 2 + 0], z0, z1);
                unpack2(acc[i * 2 + 1], z2, z3);
                z0 += xv[i].x; z1 += xv[i].y; z2 += xv[i].z; z3 += xv[i].w;
                float ig = sigm_(z0);
                float fg = sigm_(z1);
                float gg = tanh_(z2);
                float og = sigm_(z3);
                float cn = fmaf(fg, cc[i], ig * gg);
                cc[i] = cn;
                hnew[i] = og * tanh_(cn);
            }
            int u = u0 + zg;
            *(float4*)(g_hT[wr][dir] + u * BB + b0 + bgr * 4) =
                make_float4(hnew[0], hnew[1], hnew[2], hnew[3]);
#pragma unroll
            for (int i = 0; i < 4; i++) stage[(bgr * 4 + i) * 16 + zg] = hnew[i];
        }
        __syncthreads();
        // coalesced sequence output [t][b][u]
        if (tid < 128) {
            int row = tid >> 2, q = tid & 3;
            *(float4*)(outb + (size_t)(t * BB + b0 + row) * UU + u0 + q * 4) =
                ((float4*)stage)[tid];
        }

        // ---- grid-wide barrier (skew provably <= 1 step; h double-buffered) ----
        __threadfence();
        __syncthreads();
        if (tid == 0) {
            int my = g_gen;
            if (atomicAdd(&g_count, 1) == NCTA - 1) {
                g_count = 0;
                __threadfence();
                g_gen = my + 1;
            } else {
                while (g_gen == my) { }
            }
        }
        __syncthreads();
    }
}

// ---------------- merge: out[b][t][u] = 0.5*(h1f + h0f + h1b + h0b) ---------------
__global__ void merge_kernel(float* __restrict__ out) {
    int i = blockIdx.x * blockDim.x + threadIdx.x;
    if (i >= TT * BB * UU / 4) return;
    int u4 = i & 63;
    int b  = (i >> 6) & 127;
    int t  = i >> 13;
    const float4 a = ((const float4*)g_h1[0])[i];
    const float4 c = ((const float4*)g_h0[0])[i];
    const float4 d = ((const float4*)g_h1[1])[i];
    const float4 e = ((const float4*)g_h0[1])[i];
    float4 r;
    r.x = 0.5f * (a.x + c.x + d.x + e.x);
    r.y = 0.5f * (a.y + c.y + d.y + e.y);
    r.z = 0.5f * (a.z + c.z + d.z + e.z);
    r.w = 0.5f * (a.w + c.w + d.w + e.w);
    ((float4*)out)[((b * TT + t) << 6) + u4] = r;
}

// ---------------- launch ----------------------------------------------------------
extern "C" void kernel_launch(void* const* d_in, const int* in_sizes, int n_in,
                              void* d_out, int out_size) {
    const float* x   = (const float*)d_in[0];
    const float* kfw = (const float*)d_in[1];
    const float* rfw = (const float*)d_in[2];
    const float* bfw = (const float*)d_in[3];
    const float* kbw = (const float*)d_in[4];
    const float* rbw = (const float*)d_in[5];
    const float* bbw = (const float*)d_in[6];
    float* out = (float*)d_out;

    const int scan_smem = (UU * 64 + UU * 32 + 128 * 16 + 32 * 16) * (int)sizeof(float); // 108544
    cudaFuncSetAttribute(scan_kernel, cudaFuncAttributeMaxDynamicSharedMemorySize, scan_smem);

    prep_kernel<<<4096, 256>>>(kfw, rfw, bfw, kbw, rbw, bbw);
    for (int layer = 0; layer < 2; layer++) {
        proj_kernel<<<dim3(8, 256, 2), 256>>>(x, layer);
        scan_kernel<<<NCTA, 256, scan_smem>>>(layer);
    }
    merge_kernel<<<8192, 256>>>(out);
}